// round 9
// baseline (speedup 1.0000x reference)
#include <cuda_runtime.h>
#include <cstdint>

// Output: R[b, s, 64, 64] fp32, 16384 matrices of 16 KB each.
// Per matrix: 32 diagonal 2x2 rotation blocks (128 nonzero floats), zeros
// elsewhere; nonzero locations identical across matrices.
//
// One CTA (256 threads) per matrix. Each thread owns float4 slots
// tid + 256k (k=0..3): 4 unconditional coalesced zero stores plus at most
// one predicated (sin,cos)-pair overwrite to the same address (same-thread
// program order guarantees the pair lands). All stores are st.global.cs
// (evict-first): the output is a write-once stream that must not linger in
// L2 — the .cs hint shrank the dirty-drain tail by ~1.6 us in round 8.

static constexpr unsigned THREADS = 256;

__global__ void __launch_bounds__(THREADS) rope2d_final_kernel(
    const float* __restrict__ spa,   // (n_mat, 2)
    float4* __restrict__ out)        // (n_mat, 1024) float4 view
{
    unsigned tid = threadIdx.x;
    unsigned bs  = blockIdx.x;

    // ---- match decode: slot w = tid + 256k -> row = 16k + (tid>>4),
    // f4col = tid & 15. Pair slot iff f4col == 4k + (tid>>6).
    unsigned f4   = tid & 15u;
    int      diff = (int)f4 - (int)(tid >> 6);
    bool   match  = (diff >= 0) && ((diff & 3) == 0);
    unsigned km   = (unsigned)diff >> 2;            // matching k (0..3)
    unsigned row  = 16u * km + (tid >> 4);          // matched output row

    // ---- pair value (meaningful only when match) ---------------------------
    float4 pv = make_float4(0.f, 0.f, 0.f, 0.f);
    if (match) {
        float2 xy = *reinterpret_cast<const float2*>(spa + (size_t)bs * 2u);
        unsigned h = row >> 1;                      // 0..31
        float coord = (h & 16u) ? xy.y : xy.x;
        // inv_freq = 10000^(-(h%16)/16) = 2^(-(h%16)*log2(10000)/16)
        float invf = exp2f(-(float)(h & 15u) * (13.287712379549449f / 16.0f));
        float s, c;
        __sincosf(coord * invf, &s, &c);
        float a, b;
        if (row & 1u) { a = s; b = c;  }            // odd row:  (sin, cos)
        else          { a = c; b = -s; }            // even row: (cos, -sin)
        if (row & 2u) { pv.z = a; pv.w = b; }       // pair at lanes 2,3
        else          { pv.x = a; pv.y = b; }       // pair at lanes 0,1
    }

    // ---- 4 unconditional streaming zero stores + 1 predicated overwrite ----
    const float4 z = make_float4(0.f, 0.f, 0.f, 0.f);
    float4* base = out + (size_t)bs * 1024u + tid;
    #pragma unroll
    for (unsigned k = 0; k < 4; k++)
        __stcs(base + 256u * k, z);                 // st.global.cs.v4
    if (match)
        __stcs(base + 256u * km, pv);               // same addr, ordered after zero
}

extern "C" void kernel_launch(void* const* d_in, const int* in_sizes, int n_in,
                              void* d_out, int out_size)
{
    const float* spa = (const float*)d_in[0];
    float4* out = (float4*)d_out;

    unsigned n_mat = (unsigned)(out_size / 4096);   // 16384
    rope2d_final_kernel<<<n_mat, THREADS>>>(spa, out);
}

// round 10
// speedup vs baseline: 1.0057x; 1.0057x over previous
#include <cuda_runtime.h>
#include <cstdint>

// Output: R[b, s, 64, 64] fp32, 16384 matrices of 16 KB each.
// Per matrix: 32 diagonal 2x2 rotation blocks (128 nonzero floats), zeros
// elsewhere; nonzero locations identical across matrices.
//
// One CTA (256 threads) per matrix, 256-bit streaming stores (sm_10x v8):
// each thread owns two 32-byte chunks (chunk = tid + 256k, k=0..1) of the
// 512-chunk matrix. 2 unconditional v8 zero stores + at most one predicated
// v8 pair-overwrite to the same address (same-thread program order). All
// stores st.global.cs (evict-first): write-once stream, keep L2 clean.

static constexpr unsigned THREADS = 256;

static __device__ __forceinline__ void stcs_v8(float* p, const float* v) {
    asm volatile(
        "st.global.cs.v8.f32 [%0], {%1, %2, %3, %4, %5, %6, %7, %8};"
        :: "l"(p),
           "f"(v[0]), "f"(v[1]), "f"(v[2]), "f"(v[3]),
           "f"(v[4]), "f"(v[5]), "f"(v[6]), "f"(v[7])
        : "memory");
}

__global__ void __launch_bounds__(THREADS) rope2d_v8_kernel(
    const float* __restrict__ spa,   // (n_mat, 2)
    float* __restrict__ out)         // (n_mat, 4096)
{
    unsigned tid = threadIdx.x;
    unsigned bs  = blockIdx.x;

    // ---- match decode ------------------------------------------------------
    // chunk c = tid + 256k covers row = c>>3, cols [(c&7)*8, +8).
    // Pair of row r sits in sub-chunk r>>3, i.e. match iff (c&7) == (c>>6).
    // (c&7) = tid&7 ; (c>>6) = (tid>>6) + 4k  ->  diff = (tid&7)-(tid>>6),
    // match iff diff in {0,4}, k = diff>>2.
    int      diff  = (int)(tid & 7u) - (int)(tid >> 6);
    bool     match = (diff == 0) || (diff == 4);
    unsigned km    = ((unsigned)diff) >> 2;             // 0 or 1 when match
    unsigned row   = (tid + 256u * km) >> 3;            // matched output row

    // ---- pair value --------------------------------------------------------
    float pv[8] = {0.f, 0.f, 0.f, 0.f, 0.f, 0.f, 0.f, 0.f};
    if (match) {
        float2 xy = *reinterpret_cast<const float2*>(spa + (size_t)bs * 2u);
        unsigned h = row >> 1;                          // 0..31
        float coord = (h & 16u) ? xy.y : xy.x;
        // inv_freq = 10000^(-(h%16)/16) = 2^(-(h%16)*log2(10000)/16)
        float invf = exp2f(-(float)(h & 15u) * (13.287712379549449f / 16.0f));
        float s, c;
        __sincosf(coord * invf, &s, &c);
        float a, b;
        if (row & 1u) { a = s; b = c;  }                // odd row:  (sin, cos)
        else          { a = c; b = -s; }                // even row: (cos, -sin)
        unsigned pos = row & 6u;                        // pair offset in chunk
        pv[pos]     = a;
        pv[pos + 1] = b;
    }

    // ---- 2 unconditional v8 zero stores + 1 predicated v8 overwrite --------
    const float z[8] = {0.f, 0.f, 0.f, 0.f, 0.f, 0.f, 0.f, 0.f};
    float* base = out + (size_t)bs * 4096u + (size_t)tid * 8u;
    stcs_v8(base,           z);                         // chunk tid
    stcs_v8(base + 2048u,   z);                         // chunk tid + 256
    if (match)
        stcs_v8(base + 2048u * km, pv);                 // ordered after zero
}

extern "C" void kernel_launch(void* const* d_in, const int* in_sizes, int n_in,
                              void* d_out, int out_size)
{
    const float* spa = (const float*)d_in[0];
    float* out = (float*)d_out;

    unsigned n_mat = (unsigned)(out_size / 4096);   // 16384
    rope2d_v8_kernel<<<n_mat, THREADS>>>(spa, out);
}